// round 14
// baseline (speedup 1.0000x reference)
#include <cuda_runtime.h>
#include <cuda_bf16.h>
#include <cuda_fp16.h>
#include <cstdint>
#include <math.h>

#define BATCH 8192
#define DIM   1024
#define HID   512
#define EDIM  256
#define NEXP  16
#define TTASK 3

// ---------------- device scratch (no allocations allowed) ----------------
__device__ __half g_xh[(size_t)4 * BATCH * DIM];
__device__ __half g_w1[(size_t)NEXP * HID * DIM];           // [e][H][D] K-major fp16
__device__ __half g_w2[(size_t)NEXP * EDIM * HID];          // [e][E][H] K-major fp16
__device__ __half g_h [(size_t)NEXP * BATCH * HID];
__device__ __half g_eo[(size_t)NEXP * BATCH * EDIM];
__device__ float  g_gate[(size_t)TTASK * BATCH * 8];
__device__ float  g_gsh [(size_t)BATCH * 16];

// ---------------- low-level helpers ----------------
__device__ __forceinline__ uint32_t smem_u32(const void* p) {
    uint32_t a;
    asm("{ .reg .u64 t; cvta.to.shared.u64 t, %1; cvt.u32.u64 %0, t; }" : "=r"(a) : "l"(p));
    return a;
}
__device__ __forceinline__ void cp16(uint32_t s, const void* g) {
    asm volatile("cp.async.cg.shared.global [%0], [%1], 16;" :: "r"(s), "l"(g));
}
#define CP_COMMIT() asm volatile("cp.async.commit_group;" ::: "memory")
#define CP_WAIT2()  asm volatile("cp.async.wait_group 2;"  ::: "memory")

__device__ __forceinline__ void ldsm4(uint32_t (&r)[4], uint32_t a) {
    asm volatile("ldmatrix.sync.aligned.m8n8.x4.shared.b16 {%0,%1,%2,%3}, [%4];"
                 : "=r"(r[0]), "=r"(r[1]), "=r"(r[2]), "=r"(r[3]) : "r"(a));
}
__device__ __forceinline__ void mma_f16(float (&c)[4], const uint32_t (&a)[4],
                                        uint32_t b0, uint32_t b1) {
    asm volatile("mma.sync.aligned.m16n8k16.row.col.f32.f16.f16.f32 "
                 "{%0,%1,%2,%3}, {%4,%5,%6,%7}, {%8,%9}, {%0,%1,%2,%3};"
                 : "+f"(c[0]), "+f"(c[1]), "+f"(c[2]), "+f"(c[3])
                 : "r"(a[0]), "r"(a[1]), "r"(a[2]), "r"(a[3]), "r"(b0), "r"(b1));
}
__device__ __forceinline__ uint32_t pk2h(float a, float b) {
    __half2 t = __floats2half2_rn(a, b);
    return *reinterpret_cast<uint32_t*>(&t);
}

// ---------------- GEMM geometry (R13: BM=128, BN=256, 64x64 warp tiles) ------
#define RS       80u
#define A_SZ     (128u * RS)
#define B_SZ     (256u * RS)
#define OFF_B    A_SZ
#define STG_SZ   (A_SZ + B_SZ)        // 30720 B per stage
#define NSTG     5
#define BIAS_OFF (NSTG * STG_SZ)      // 153600
#define SMEM_TT  (BIAS_OFF + 1024)

template<int K, int OUTN, bool SPLIT_OUT>
__global__ void __launch_bounds__(256) gemm_kernel(
    const __half* __restrict__ A, const __half* __restrict__ B,
    const float* __restrict__ bias_spec, const float* __restrict__ bias_sh)
{
    constexpr int KIT = K / 32;
    extern __shared__ __align__(16) char smem[];
    const uint32_t sb = smem_u32(smem);
    const int tid = threadIdx.x;
    const int e  = blockIdx.z;
    const int bm = blockIdx.y * 128;
    const int bn = blockIdx.x * 256;
    const int zA = SPLIT_OUT ? (e < 12 ? (e >> 2) : 3) : e;

    float* bias_sm = (float*)(smem + BIAS_OFF);
    {
        const float* bias = (e < 12) ? bias_spec + (size_t)e * OUTN
                                     : bias_sh  + (size_t)(e - 12) * OUTN;
        bias_sm[tid] = bias[bn + tid];
    }

    const __half* gA = A + ((size_t)zA * BATCH + bm) * K;
    const __half* gB = B + ((size_t)e * OUTN + bn) * K;

    auto load_stage = [&](int s, int k0) {
        const uint32_t st = sb + (uint32_t)s * STG_SZ;
        #pragma unroll
        for (int i = 0; i < 2; i++) {
            const int c = tid + i * 256;
            const int row = c >> 2, q = c & 3;
            cp16(st + (uint32_t)row * RS + (uint32_t)q * 16,
                 gA + (size_t)row * K + k0 + q * 8);
        }
        #pragma unroll
        for (int i = 0; i < 4; i++) {
            const int c = tid + i * 256;
            const int row = c >> 2, q = c & 3;
            cp16(st + OFF_B + (uint32_t)row * RS + (uint32_t)q * 16,
                 gB + (size_t)row * K + k0 + q * 8);
        }
        CP_COMMIT();
    };

    load_stage(0, 0);
    load_stage(1, 32);
    load_stage(2, 64);
    load_stage(3, 96);

    const int wid = tid >> 5, L = tid & 31;
    const int mbase = (wid >> 2) * 64;
    const int nbase = (wid & 3) * 64;

    float acc[4][8][4];
    #pragma unroll
    for (int i = 0; i < 4; i++)
        #pragma unroll
        for (int j = 0; j < 8; j++)
            #pragma unroll
            for (int q = 0; q < 4; q++) acc[i][j][q] = 0.0f;

    const uint32_t aoff = (uint32_t)(mbase + (L & 15)) * RS + (uint32_t)(((L >> 4) & 1) * 16);
    const uint32_t boff = (uint32_t)(nbase + (L & 7) + ((L >> 4) & 1) * 8) * RS
                        + (uint32_t)(((L >> 3) & 1) * 16);

    uint32_t a0f[4][4], b0f[4][4], a1f[4][4], b1f[4][4];

    CP_WAIT2();
    __syncthreads();
    {
        const uint32_t ka = sb + aoff, kb = sb + OFF_B + boff;
        #pragma unroll
        for (int mt = 0; mt < 4; mt++) ldsm4(a0f[mt], ka + mt * (16 * RS));
        #pragma unroll
        for (int nt2 = 0; nt2 < 4; nt2++) ldsm4(b0f[nt2], kb + nt2 * (16 * RS));
    }

    int rstage = 0;
    for (int kt = 0; kt < KIT; kt++) {
        __syncthreads();
        const int wstage = (rstage + 4 >= NSTG) ? rstage - 1 : rstage + 4;
        if (kt + 4 < KIT) load_stage(wstage, (kt + 4) * 32);
        else              CP_COMMIT();

        const uint32_t sbase = sb + (uint32_t)rstage * STG_SZ;
        const int nstage = (rstage == 4) ? 0 : rstage + 1;
        const uint32_t nb2 = sb + (uint32_t)nstage * STG_SZ;

        {
            const uint32_t ka = sbase + aoff + 32, kb = sbase + OFF_B + boff + 32;
            #pragma unroll
            for (int mt = 0; mt < 4; mt++) ldsm4(a1f[mt], ka + mt * (16 * RS));
            #pragma unroll
            for (int nt2 = 0; nt2 < 4; nt2++) ldsm4(b1f[nt2], kb + nt2 * (16 * RS));
        }
        #pragma unroll
        for (int mt = 0; mt < 4; mt++)
            #pragma unroll
            for (int nt = 0; nt < 8; nt++)
                mma_f16(acc[mt][nt], a0f[mt],
                        b0f[nt >> 1][(nt & 1) * 2], b0f[nt >> 1][(nt & 1) * 2 + 1]);

        CP_WAIT2();
        if (kt + 1 < KIT) {
            const uint32_t ka = nb2 + aoff, kb = nb2 + OFF_B + boff;
            #pragma unroll
            for (int mt = 0; mt < 4; mt++) ldsm4(a0f[mt], ka + mt * (16 * RS));
            #pragma unroll
            for (int nt2 = 0; nt2 < 4; nt2++) ldsm4(b0f[nt2], kb + nt2 * (16 * RS));
        }
        #pragma unroll
        for (int mt = 0; mt < 4; mt++)
            #pragma unroll
            for (int nt = 0; nt < 8; nt++)
                mma_f16(acc[mt][nt], a1f[mt],
                        b1f[nt >> 1][(nt & 1) * 2], b1f[nt >> 1][(nt & 1) * 2 + 1]);

        rstage = nstage;
    }

    const int g  = L >> 2;
    const int t2 = (L & 3) * 2;
    #pragma unroll
    for (int mt = 0; mt < 4; mt++) {
        const int r0 = bm + mbase + mt * 16 + g;
        #pragma unroll
        for (int nt = 0; nt < 8; nt++) {
            const int col = nbase + nt * 8 + t2;
            const float b0v = bias_sm[col], b1v = bias_sm[col + 1];
            float v00 = fmaxf(acc[mt][nt][0] + b0v, 0.0f);
            float v01 = fmaxf(acc[mt][nt][1] + b1v, 0.0f);
            float v10 = fmaxf(acc[mt][nt][2] + b0v, 0.0f);
            float v11 = fmaxf(acc[mt][nt][3] + b1v, 0.0f);
            const size_t o0 = ((size_t)e * BATCH + r0) * OUTN + bn + col;
            const size_t o1 = o0 + (size_t)8 * OUTN;
            if (SPLIT_OUT) {
                *reinterpret_cast<uint32_t*>(&g_h[o0]) = pk2h(v00, v01);
                *reinterpret_cast<uint32_t*>(&g_h[o1]) = pk2h(v10, v11);
            } else {
                *reinterpret_cast<uint32_t*>(&g_eo[o0]) = pk2h(v00, v01);
                *reinterpret_cast<uint32_t*>(&g_eo[o1]) = pk2h(v10, v11);
            }
        }
    }
}

// ---------------- input convert: fp32 -> fp16 (critical path, cheap) --------
__global__ __launch_bounds__(256) void convert_x_kernel(
    const float* __restrict__ xt, const float* __restrict__ xs)
{
    const size_t i = (size_t)blockIdx.x * blockDim.x + threadIdx.x;
    const size_t base = i * 4;
    const size_t T3 = (size_t)3 * BATCH * DIM;
    float4 v = (base < T3) ? *(const float4*)(xt + base)
                           : *(const float4*)(xs + base - T3);
    uint2 H = { pk2h(v.x, v.y), pk2h(v.z, v.w) };
    *reinterpret_cast<uint2*>(&g_xh[base]) = H;
}

// ---------------- weight transpose + convert: [e][K][N] -> [e][N][K] fp16 ----
__global__ __launch_bounds__(256) void wtrans_kernel(
    const float* __restrict__ Wsp, const float* __restrict__ Wsh,
    __half* __restrict__ dst, int K, int N)
{
    __shared__ float t[32][33];
    const int e = blockIdx.z;
    const float* src = (e < 12) ? Wsp + (size_t)e * K * N
                                : Wsh + (size_t)(e - 12) * K * N;
    const int n0 = blockIdx.x * 32, k0 = blockIdx.y * 32;
    const int c = threadIdx.x & 31, r8 = threadIdx.x >> 5;
    #pragma unroll
    for (int rr = 0; rr < 32; rr += 8)
        t[r8 + rr][c] = src[(size_t)(k0 + r8 + rr) * N + n0 + c];
    __syncthreads();
    #pragma unroll
    for (int rr = 0; rr < 32; rr += 8) {
        float v = t[c][r8 + rr];
        size_t o = ((size_t)e * N + n0 + r8 + rr) * K + k0 + c;
        dst[o] = __float2half_rn(v);
    }
}

// ---------------- gates (pure; runs concurrent with gemm1) ----------------
// 8 rows/warp (task), 4 rows/warp (shared). Gate math in fp32.
#define TASK_WARPS (TTASK * BATCH / 8)   // 3072
#define SH_WARPS   (BATCH / 4)           // 2048
__global__ __launch_bounds__(256) void gates_kernel(
    const float* __restrict__ x_tasks, const float* __restrict__ x_shared,
    const float* __restrict__ W_gate,  const float* __restrict__ b_gate,
    const float* __restrict__ W_gsh,   const float* __restrict__ b_gsh)
{
    const int warp = (blockIdx.x * blockDim.x + threadIdx.x) >> 5;
    const int lane = threadIdx.x & 31;

    if (warp < TASK_WARPS) {
        const int r0 = warp * 8;
        const int t  = r0 >> 13;
        const int b0 = r0 & (BATCH - 1);
        const float* x = x_tasks + ((size_t)t * BATCH + b0) * DIM;
        const float* W = W_gate + (size_t)t * DIM * 8;
        float s[8][8];
        #pragma unroll
        for (int r = 0; r < 8; r++)
            #pragma unroll
            for (int o = 0; o < 8; o++) s[r][o] = 0.0f;
        for (int d = lane; d < DIM; d += 32) {
            float4 w0 = *(const float4*)(W + (size_t)d * 8);
            float4 w1 = *(const float4*)(W + (size_t)d * 8 + 4);
            #pragma unroll
            for (int r = 0; r < 8; r++) {
                float xv = x[(size_t)r * DIM + d];
                s[r][0] += xv * w0.x; s[r][1] += xv * w0.y;
                s[r][2] += xv * w0.z; s[r][3] += xv * w0.w;
                s[r][4] += xv * w1.x; s[r][5] += xv * w1.y;
                s[r][6] += xv * w1.z; s[r][7] += xv * w1.w;
            }
        }
        #pragma unroll
        for (int r = 0; r < 8; r++)
            #pragma unroll
            for (int o = 0; o < 8; o++)
                #pragma unroll
                for (int off = 16; off > 0; off >>= 1)
                    s[r][o] += __shfl_xor_sync(0xffffffffu, s[r][o], off);
        if (lane == 0) {
            #pragma unroll
            for (int r = 0; r < 8; r++) {
                float mx = -1e30f;
                #pragma unroll
                for (int o = 0; o < 8; o++) { s[r][o] += b_gate[t * 8 + o]; mx = fmaxf(mx, s[r][o]); }
                float sum = 0.0f;
                #pragma unroll
                for (int o = 0; o < 8; o++) { s[r][o] = expf(s[r][o] - mx); sum += s[r][o]; }
                float inv = 1.0f / sum;
                #pragma unroll
                for (int o = 0; o < 8; o++)
                    g_gate[((size_t)t * BATCH + b0 + r) * 8 + o] = s[r][o] * inv;
            }
        }
    } else {
        const int b0 = (warp - TASK_WARPS) * 4;
        const float* x = x_shared + (size_t)b0 * DIM;
        float s[4][16];
        #pragma unroll
        for (int r = 0; r < 4; r++)
            #pragma unroll
            for (int o = 0; o < 16; o++) s[r][o] = 0.0f;
        for (int d = lane; d < DIM; d += 32) {
            float4 w0 = *(const float4*)(W_gsh + (size_t)d * 16);
            float4 w1 = *(const float4*)(W_gsh + (size_t)d * 16 + 4);
            float4 w2 = *(const float4*)(W_gsh + (size_t)d * 16 + 8);
            float4 w3 = *(const float4*)(W_gsh + (size_t)d * 16 + 12);
            #pragma unroll
            for (int r = 0; r < 4; r++) {
                float xv = x[(size_t)r * DIM + d];
                s[r][ 0] += xv * w0.x; s[r][ 1] += xv * w0.y; s[r][ 2] += xv * w0.z; s[r][ 3] += xv * w0.w;
                s[r][ 4] += xv * w1.x; s[r][ 5] += xv * w1.y; s[r][ 6] += xv * w1.z; s[r][ 7] += xv * w1.w;
                s[r][ 8] += xv * w2.x; s[r][ 9] += xv * w2.y; s[r][10] += xv * w2.z; s[r][11] += xv * w2.w;
                s[r][12] += xv * w3.x; s[r][13] += xv * w3.y; s[r][14] += xv * w3.z; s[r][15] += xv * w3.w;
            }
        }
        #pragma unroll
        for (int r = 0; r < 4; r++)
            #pragma unroll
            for (int o = 0; o < 16; o++)
                #pragma unroll
                for (int off = 16; off > 0; off >>= 1)
                    s[r][o] += __shfl_xor_sync(0xffffffffu, s[r][o], off);
        if (lane == 0) {
            #pragma unroll
            for (int r = 0; r < 4; r++) {
                float mx = -1e30f;
                #pragma unroll
                for (int o = 0; o < 16; o++) { s[r][o] += b_gsh[o]; mx = fmaxf(mx, s[r][o]); }
                float sum = 0.0f;
                #pragma unroll
                for (int o = 0; o < 16; o++) { s[r][o] = expf(s[r][o] - mx); sum += s[r][o]; }
                float inv = 1.0f / sum;
                #pragma unroll
                for (int o = 0; o < 16; o++)
                    g_gsh[(size_t)(b0 + r) * 16 + o] = s[r][o] * inv;
            }
        }
    }
}

// ---------------- combine (eo in fp16) ----------------
__global__ __launch_bounds__(256) void combine_kernel(float* __restrict__ out)
{
    const int b = blockIdx.x;
    const int e = threadIdx.x;
    __shared__ float g[24];
    __shared__ float gs[16];

    if (threadIdx.x < 24)
        g[threadIdx.x] = g_gate[(size_t)(threadIdx.x >> 3) * BATCH * 8
                                + (size_t)b * 8 + (threadIdx.x & 7)];
    if (threadIdx.x >= 32 && threadIdx.x < 48)
        gs[threadIdx.x - 32] = g_gsh[(size_t)b * 16 + (threadIdx.x - 32)];
    __syncthreads();

    float a0 = 0.0f, a1 = 0.0f, a2 = 0.0f, a3 = 0.0f;
    const __half* eo = g_eo + (size_t)b * EDIM + e;

    #pragma unroll
    for (int j = 0; j < 12; j++) {
        float v = __half2float(eo[(size_t)j * BATCH * EDIM]);
        const int t = j >> 2;
        float gw = g[t * 8 + (j & 3)];
        if (t == 0)      a0 += gw * v;
        else if (t == 1) a1 += gw * v;
        else             a2 += gw * v;
        a3 += gs[j] * v;
    }
    #pragma unroll
    for (int s = 0; s < 4; s++) {
        float v = __half2float(eo[(size_t)(12 + s) * BATCH * EDIM]);
        a0 += g[0 * 8 + 4 + s] * v;
        a1 += g[1 * 8 + 4 + s] * v;
        a2 += g[2 * 8 + 4 + s] * v;
        a3 += gs[12 + s] * v;
    }

    const size_t o = (size_t)b * EDIM + e;
    const size_t plane = (size_t)BATCH * EDIM;
    out[o]             = a0;
    out[plane + o]     = a1;
    out[2 * plane + o] = a2;
    out[3 * plane + o] = a3;
}

// ---------------- host ----------------
extern "C" void kernel_launch(void* const* d_in, const int* in_sizes, int n_in,
                              void* d_out, int out_size)
{
    const float* x_tasks  = (const float*)d_in[0];
    const float* x_shared = (const float*)d_in[1];
    const float* W_spec1  = (const float*)d_in[2];
    const float* b_spec1  = (const float*)d_in[3];
    const float* W_spec2  = (const float*)d_in[4];
    const float* b_spec2  = (const float*)d_in[5];
    const float* W_sh1    = (const float*)d_in[6];
    const float* b_sh1    = (const float*)d_in[7];
    const float* W_sh2    = (const float*)d_in[8];
    const float* b_sh2    = (const float*)d_in[9];
    const float* W_gate   = (const float*)d_in[10];
    const float* b_gate   = (const float*)d_in[11];
    const float* W_gsh    = (const float*)d_in[12];
    const float* b_gsh    = (const float*)d_in[13];
    float* out = (float*)d_out;

    void *p_xh, *p_w1, *p_w2, *p_h;
    cudaGetSymbolAddress(&p_xh, g_xh);
    cudaGetSymbolAddress(&p_w1, g_w1);
    cudaGetSymbolAddress(&p_w2, g_w2);
    cudaGetSymbolAddress(&p_h, g_h);

    // one-time infra (created on the uncaptured correctness call; reused after)
    static bool inited = false;
    static cudaStream_t s1, s2;
    static cudaEvent_t ev_root, ev_w1, ev_w2, ev_gates;
    if (!inited) {
        cudaStreamCreateWithFlags(&s1, cudaStreamNonBlocking);
        cudaStreamCreateWithFlags(&s2, cudaStreamNonBlocking);
        cudaEventCreateWithFlags(&ev_root,  cudaEventDisableTiming);
        cudaEventCreateWithFlags(&ev_w1,    cudaEventDisableTiming);
        cudaEventCreateWithFlags(&ev_w2,    cudaEventDisableTiming);
        cudaEventCreateWithFlags(&ev_gates, cudaEventDisableTiming);
        cudaFuncSetAttribute(gemm_kernel<1024, HID, true>,
                             cudaFuncAttributeMaxDynamicSharedMemorySize, SMEM_TT);
        cudaFuncSetAttribute(gemm_kernel<512, EDIM, false>,
                             cudaFuncAttributeMaxDynamicSharedMemorySize, SMEM_TT);
        inited = true;
    }

    // fork side streams off the main (capture) stream
    cudaEventRecord(ev_root, 0);
    cudaStreamWaitEvent(s1, ev_root, 0);
    cudaStreamWaitEvent(s2, ev_root, 0);

    // s1: weight transposes (w1 gates gemm1; w2 gates gemm2)
    wtrans_kernel<<<dim3(HID / 32, DIM / 32, NEXP), 256, 0, s1>>>(
        W_spec1, W_sh1, (__half*)p_w1, DIM, HID);
    cudaEventRecord(ev_w1, s1);
    wtrans_kernel<<<dim3(EDIM / 32, HID / 32, NEXP), 256, 0, s1>>>(
        W_spec2, W_sh2, (__half*)p_w2, HID, EDIM);
    cudaEventRecord(ev_w2, s1);

    // s2: gates (needed only by combine) — overlaps gemm1
    gates_kernel<<<(TASK_WARPS + SH_WARPS) / 8, 256, 0, s2>>>(
        x_tasks, x_shared, W_gate, b_gate, W_gsh, b_gsh);
    cudaEventRecord(ev_gates, s2);

    // main stream: x convert -> gemm1 -> gemm2 -> combine
    convert_x_kernel<<<(4u * BATCH * DIM / 4) / 256, 256>>>(x_tasks, x_shared);

    cudaStreamWaitEvent(0, ev_w1, 0);
    gemm_kernel<1024, HID, true><<<dim3(HID / 256, BATCH / 128, NEXP), 256, SMEM_TT>>>(
        (const __half*)p_xh, (const __half*)p_w1, b_spec1, b_sh1);

    cudaStreamWaitEvent(0, ev_w2, 0);
    gemm_kernel<512, EDIM, false><<<dim3(EDIM / 256, BATCH / 128, NEXP), 256, SMEM_TT>>>(
        (const __half*)p_h, (const __half*)p_w2, b_spec2, b_sh2);

    cudaStreamWaitEvent(0, ev_gates, 0);
    combine_kernel<<<BATCH, 256>>>(out);
}

// round 15
// speedup vs baseline: 1.0028x; 1.0028x over previous
#include <cuda_runtime.h>
#include <cuda_bf16.h>
#include <cuda_fp16.h>
#include <cstdint>
#include <math.h>

#define BATCH 8192
#define DIM   1024
#define HID   512
#define EDIM  256
#define NEXP  16
#define TTASK 3

// ---------------- device scratch (no allocations allowed) ----------------
__device__ __half g_xh[(size_t)4 * BATCH * DIM];
__device__ __half g_w1[(size_t)NEXP * HID * DIM];           // [e][H][D] K-major fp16
__device__ __half g_w2[(size_t)NEXP * EDIM * HID];          // [e][E][H] K-major fp16
__device__ __half g_h [(size_t)NEXP * BATCH * HID];
__device__ __half g_eo[(size_t)NEXP * BATCH * EDIM];
__device__ float  g_gate[(size_t)TTASK * BATCH * 8];
__device__ float  g_gsh [(size_t)BATCH * 16];

// ---------------- low-level helpers ----------------
__device__ __forceinline__ uint32_t smem_u32(const void* p) {
    uint32_t a;
    asm("{ .reg .u64 t; cvta.to.shared.u64 t, %1; cvt.u32.u64 %0, t; }" : "=r"(a) : "l"(p));
    return a;
}
__device__ __forceinline__ void cp16(uint32_t s, const void* g) {
    asm volatile("cp.async.cg.shared.global [%0], [%1], 16;" :: "r"(s), "l"(g));
}
#define CP_COMMIT() asm volatile("cp.async.commit_group;" ::: "memory")
#define CP_WAIT2()  asm volatile("cp.async.wait_group 2;"  ::: "memory")

__device__ __forceinline__ void ldsm4(uint32_t (&r)[4], uint32_t a) {
    asm volatile("ldmatrix.sync.aligned.m8n8.x4.shared.b16 {%0,%1,%2,%3}, [%4];"
                 : "=r"(r[0]), "=r"(r[1]), "=r"(r[2]), "=r"(r[3]) : "r"(a));
}
__device__ __forceinline__ void mma_f16(float (&c)[4], const uint32_t (&a)[4],
                                        uint32_t b0, uint32_t b1) {
    asm volatile("mma.sync.aligned.m16n8k16.row.col.f32.f16.f16.f32 "
                 "{%0,%1,%2,%3}, {%4,%5,%6,%7}, {%8,%9}, {%0,%1,%2,%3};"
                 : "+f"(c[0]), "+f"(c[1]), "+f"(c[2]), "+f"(c[3])
                 : "r"(a[0]), "r"(a[1]), "r"(a[2]), "r"(a[3]), "r"(b0), "r"(b1));
}
__device__ __forceinline__ uint32_t pk2h(float a, float b) {
    __half2 t = __floats2half2_rn(a, b);
    return *reinterpret_cast<uint32_t*>(&t);
}

// ---------------- GEMM geometry (R13: BM=128, BN=256, 64x64 warp tiles) ------
#define RS       80u
#define A_SZ     (128u * RS)
#define B_SZ     (256u * RS)
#define OFF_B    A_SZ
#define STG_SZ   (A_SZ + B_SZ)        // 30720 B per stage
#define NSTG     5
#define BIAS_OFF (NSTG * STG_SZ)      // 153600
#define SMEM_TT  (BIAS_OFF + 1024)

template<int K, int OUTN, bool SPLIT_OUT>
__global__ void __launch_bounds__(256) gemm_kernel(
    const __half* __restrict__ A, const __half* __restrict__ B,
    const float* __restrict__ bias_spec, const float* __restrict__ bias_sh)
{
    constexpr int KIT = K / 32;
    extern __shared__ __align__(16) char smem[];
    const uint32_t sb = smem_u32(smem);
    const int tid = threadIdx.x;
    const int e  = blockIdx.z;
    const int bm = blockIdx.y * 128;
    const int bn = blockIdx.x * 256;
    const int zA = SPLIT_OUT ? (e < 12 ? (e >> 2) : 3) : e;

    float* bias_sm = (float*)(smem + BIAS_OFF);
    {
        const float* bias = (e < 12) ? bias_spec + (size_t)e * OUTN
                                     : bias_sh  + (size_t)(e - 12) * OUTN;
        bias_sm[tid] = bias[bn + tid];
    }

    const __half* gA = A + ((size_t)zA * BATCH + bm) * K;
    const __half* gB = B + ((size_t)e * OUTN + bn) * K;

    auto load_stage = [&](int s, int k0) {
        const uint32_t st = sb + (uint32_t)s * STG_SZ;
        #pragma unroll
        for (int i = 0; i < 2; i++) {
            const int c = tid + i * 256;
            const int row = c >> 2, q = c & 3;
            cp16(st + (uint32_t)row * RS + (uint32_t)q * 16,
                 gA + (size_t)row * K + k0 + q * 8);
        }
        #pragma unroll
        for (int i = 0; i < 4; i++) {
            const int c = tid + i * 256;
            const int row = c >> 2, q = c & 3;
            cp16(st + OFF_B + (uint32_t)row * RS + (uint32_t)q * 16,
                 gB + (size_t)row * K + k0 + q * 8);
        }
        CP_COMMIT();
    };

    load_stage(0, 0);
    load_stage(1, 32);
    load_stage(2, 64);
    load_stage(3, 96);

    const int wid = tid >> 5, L = tid & 31;
    const int mbase = (wid >> 2) * 64;
    const int nbase = (wid & 3) * 64;

    float acc[4][8][4];
    #pragma unroll
    for (int i = 0; i < 4; i++)
        #pragma unroll
        for (int j = 0; j < 8; j++)
            #pragma unroll
            for (int q = 0; q < 4; q++) acc[i][j][q] = 0.0f;

    const uint32_t aoff = (uint32_t)(mbase + (L & 15)) * RS + (uint32_t)(((L >> 4) & 1) * 16);
    const uint32_t boff = (uint32_t)(nbase + (L & 7) + ((L >> 4) & 1) * 8) * RS
                        + (uint32_t)(((L >> 3) & 1) * 16);

    uint32_t a0f[4][4], b0f[4][4], a1f[4][4], b1f[4][4];

    CP_WAIT2();
    __syncthreads();
    {
        const uint32_t ka = sb + aoff, kb = sb + OFF_B + boff;
        #pragma unroll
        for (int mt = 0; mt < 4; mt++) ldsm4(a0f[mt], ka + mt * (16 * RS));
        #pragma unroll
        for (int nt2 = 0; nt2 < 4; nt2++) ldsm4(b0f[nt2], kb + nt2 * (16 * RS));
    }

    int rstage = 0;
    for (int kt = 0; kt < KIT; kt++) {
        __syncthreads();
        const int wstage = (rstage + 4 >= NSTG) ? rstage - 1 : rstage + 4;
        if (kt + 4 < KIT) load_stage(wstage, (kt + 4) * 32);
        else              CP_COMMIT();

        const uint32_t sbase = sb + (uint32_t)rstage * STG_SZ;
        const int nstage = (rstage == 4) ? 0 : rstage + 1;
        const uint32_t nb2 = sb + (uint32_t)nstage * STG_SZ;

        {
            const uint32_t ka = sbase + aoff + 32, kb = sbase + OFF_B + boff + 32;
            #pragma unroll
            for (int mt = 0; mt < 4; mt++) ldsm4(a1f[mt], ka + mt * (16 * RS));
            #pragma unroll
            for (int nt2 = 0; nt2 < 4; nt2++) ldsm4(b1f[nt2], kb + nt2 * (16 * RS));
        }
        #pragma unroll
        for (int mt = 0; mt < 4; mt++)
            #pragma unroll
            for (int nt = 0; nt < 8; nt++)
                mma_f16(acc[mt][nt], a0f[mt],
                        b0f[nt >> 1][(nt & 1) * 2], b0f[nt >> 1][(nt & 1) * 2 + 1]);

        CP_WAIT2();
        if (kt + 1 < KIT) {
            const uint32_t ka = nb2 + aoff, kb = nb2 + OFF_B + boff;
            #pragma unroll
            for (int mt = 0; mt < 4; mt++) ldsm4(a0f[mt], ka + mt * (16 * RS));
            #pragma unroll
            for (int nt2 = 0; nt2 < 4; nt2++) ldsm4(b0f[nt2], kb + nt2 * (16 * RS));
        }
        #pragma unroll
        for (int mt = 0; mt < 4; mt++)
            #pragma unroll
            for (int nt = 0; nt < 8; nt++)
                mma_f16(acc[mt][nt], a1f[mt],
                        b1f[nt >> 1][(nt & 1) * 2], b1f[nt >> 1][(nt & 1) * 2 + 1]);

        rstage = nstage;
    }

    const int g  = L >> 2;
    const int t2 = (L & 3) * 2;
    #pragma unroll
    for (int mt = 0; mt < 4; mt++) {
        const int r0 = bm + mbase + mt * 16 + g;
        #pragma unroll
        for (int nt = 0; nt < 8; nt++) {
            const int col = nbase + nt * 8 + t2;
            const float b0v = bias_sm[col], b1v = bias_sm[col + 1];
            float v00 = fmaxf(acc[mt][nt][0] + b0v, 0.0f);
            float v01 = fmaxf(acc[mt][nt][1] + b1v, 0.0f);
            float v10 = fmaxf(acc[mt][nt][2] + b0v, 0.0f);
            float v11 = fmaxf(acc[mt][nt][3] + b1v, 0.0f);
            const size_t o0 = ((size_t)e * BATCH + r0) * OUTN + bn + col;
            const size_t o1 = o0 + (size_t)8 * OUTN;
            if (SPLIT_OUT) {
                *reinterpret_cast<uint32_t*>(&g_h[o0]) = pk2h(v00, v01);
                *reinterpret_cast<uint32_t*>(&g_h[o1]) = pk2h(v10, v11);
            } else {
                *reinterpret_cast<uint32_t*>(&g_eo[o0]) = pk2h(v00, v01);
                *reinterpret_cast<uint32_t*>(&g_eo[o1]) = pk2h(v10, v11);
            }
        }
    }
}

// ---------------- input convert: fp32 -> fp16 (critical path, cheap) --------
__global__ __launch_bounds__(256) void convert_x_kernel(
    const float* __restrict__ xt, const float* __restrict__ xs)
{
    const size_t i = (size_t)blockIdx.x * blockDim.x + threadIdx.x;
    const size_t base = i * 4;
    const size_t T3 = (size_t)3 * BATCH * DIM;
    float4 v = (base < T3) ? *(const float4*)(xt + base)
                           : *(const float4*)(xs + base - T3);
    uint2 H = { pk2h(v.x, v.y), pk2h(v.z, v.w) };
    *reinterpret_cast<uint2*>(&g_xh[base]) = H;
}

// ---------------- weight transpose + convert: [e][K][N] -> [e][N][K] fp16 ----
__global__ __launch_bounds__(256) void wtrans_kernel(
    const float* __restrict__ Wsp, const float* __restrict__ Wsh,
    __half* __restrict__ dst, int K, int N)
{
    __shared__ float t[32][33];
    const int e = blockIdx.z;
    const float* src = (e < 12) ? Wsp + (size_t)e * K * N
                                : Wsh + (size_t)(e - 12) * K * N;
    const int n0 = blockIdx.x * 32, k0 = blockIdx.y * 32;
    const int c = threadIdx.x & 31, r8 = threadIdx.x >> 5;
    #pragma unroll
    for (int rr = 0; rr < 32; rr += 8)
        t[r8 + rr][c] = src[(size_t)(k0 + r8 + rr) * N + n0 + c];
    __syncthreads();
    #pragma unroll
    for (int rr = 0; rr < 32; rr += 8) {
        float v = t[c][r8 + rr];
        size_t o = ((size_t)e * N + n0 + r8 + rr) * K + k0 + c;
        dst[o] = __float2half_rn(v);
    }
}

// ---------------- gates (pure; 128-thread blocks to co-reside with gemm1) ----
// 8 rows/warp (task), 4 rows/warp (shared). Gate math in fp32.
#define TASK_WARPS (TTASK * BATCH / 8)   // 3072
#define SH_WARPS   (BATCH / 4)           // 2048
__global__ __launch_bounds__(128) void gates_kernel(
    const float* __restrict__ x_tasks, const float* __restrict__ x_shared,
    const float* __restrict__ W_gate,  const float* __restrict__ b_gate,
    const float* __restrict__ W_gsh,   const float* __restrict__ b_gsh)
{
    const int warp = (blockIdx.x * blockDim.x + threadIdx.x) >> 5;
    const int lane = threadIdx.x & 31;

    if (warp < TASK_WARPS) {
        const int r0 = warp * 8;
        const int t  = r0 >> 13;
        const int b0 = r0 & (BATCH - 1);
        const float* x = x_tasks + ((size_t)t * BATCH + b0) * DIM;
        const float* W = W_gate + (size_t)t * DIM * 8;
        float s[8][8];
        #pragma unroll
        for (int r = 0; r < 8; r++)
            #pragma unroll
            for (int o = 0; o < 8; o++) s[r][o] = 0.0f;
        for (int d = lane; d < DIM; d += 32) {
            float4 w0 = *(const float4*)(W + (size_t)d * 8);
            float4 w1 = *(const float4*)(W + (size_t)d * 8 + 4);
            #pragma unroll
            for (int r = 0; r < 8; r++) {
                float xv = x[(size_t)r * DIM + d];
                s[r][0] += xv * w0.x; s[r][1] += xv * w0.y;
                s[r][2] += xv * w0.z; s[r][3] += xv * w0.w;
                s[r][4] += xv * w1.x; s[r][5] += xv * w1.y;
                s[r][6] += xv * w1.z; s[r][7] += xv * w1.w;
            }
        }
        #pragma unroll
        for (int r = 0; r < 8; r++)
            #pragma unroll
            for (int o = 0; o < 8; o++)
                #pragma unroll
                for (int off = 16; off > 0; off >>= 1)
                    s[r][o] += __shfl_xor_sync(0xffffffffu, s[r][o], off);
        if (lane == 0) {
            #pragma unroll
            for (int r = 0; r < 8; r++) {
                float mx = -1e30f;
                #pragma unroll
                for (int o = 0; o < 8; o++) { s[r][o] += b_gate[t * 8 + o]; mx = fmaxf(mx, s[r][o]); }
                float sum = 0.0f;
                #pragma unroll
                for (int o = 0; o < 8; o++) { s[r][o] = expf(s[r][o] - mx); sum += s[r][o]; }
                float inv = 1.0f / sum;
                #pragma unroll
                for (int o = 0; o < 8; o++)
                    g_gate[((size_t)t * BATCH + b0 + r) * 8 + o] = s[r][o] * inv;
            }
        }
    } else {
        const int b0 = (warp - TASK_WARPS) * 4;
        const float* x = x_shared + (size_t)b0 * DIM;
        float s[4][16];
        #pragma unroll
        for (int r = 0; r < 4; r++)
            #pragma unroll
            for (int o = 0; o < 16; o++) s[r][o] = 0.0f;
        for (int d = lane; d < DIM; d += 32) {
            float4 w0 = *(const float4*)(W_gsh + (size_t)d * 16);
            float4 w1 = *(const float4*)(W_gsh + (size_t)d * 16 + 4);
            float4 w2 = *(const float4*)(W_gsh + (size_t)d * 16 + 8);
            float4 w3 = *(const float4*)(W_gsh + (size_t)d * 16 + 12);
            #pragma unroll
            for (int r = 0; r < 4; r++) {
                float xv = x[(size_t)r * DIM + d];
                s[r][ 0] += xv * w0.x; s[r][ 1] += xv * w0.y; s[r][ 2] += xv * w0.z; s[r][ 3] += xv * w0.w;
                s[r][ 4] += xv * w1.x; s[r][ 5] += xv * w1.y; s[r][ 6] += xv * w1.z; s[r][ 7] += xv * w1.w;
                s[r][ 8] += xv * w2.x; s[r][ 9] += xv * w2.y; s[r][10] += xv * w2.z; s[r][11] += xv * w2.w;
                s[r][12] += xv * w3.x; s[r][13] += xv * w3.y; s[r][14] += xv * w3.z; s[r][15] += xv * w3.w;
            }
        }
        #pragma unroll
        for (int r = 0; r < 4; r++)
            #pragma unroll
            for (int o = 0; o < 16; o++)
                #pragma unroll
                for (int off = 16; off > 0; off >>= 1)
                    s[r][o] += __shfl_xor_sync(0xffffffffu, s[r][o], off);
        if (lane == 0) {
            #pragma unroll
            for (int r = 0; r < 4; r++) {
                float mx = -1e30f;
                #pragma unroll
                for (int o = 0; o < 16; o++) { s[r][o] += b_gsh[o]; mx = fmaxf(mx, s[r][o]); }
                float sum = 0.0f;
                #pragma unroll
                for (int o = 0; o < 16; o++) { s[r][o] = expf(s[r][o] - mx); sum += s[r][o]; }
                float inv = 1.0f / sum;
                #pragma unroll
                for (int o = 0; o < 16; o++)
                    g_gsh[(size_t)(b0 + r) * 16 + o] = s[r][o] * inv;
            }
        }
    }
}

// ---------------- combine (eo in fp16) ----------------
__global__ __launch_bounds__(256) void combine_kernel(float* __restrict__ out)
{
    const int b = blockIdx.x;
    const int e = threadIdx.x;
    __shared__ float g[24];
    __shared__ float gs[16];

    if (threadIdx.x < 24)
        g[threadIdx.x] = g_gate[(size_t)(threadIdx.x >> 3) * BATCH * 8
                                + (size_t)b * 8 + (threadIdx.x & 7)];
    if (threadIdx.x >= 32 && threadIdx.x < 48)
        gs[threadIdx.x - 32] = g_gsh[(size_t)b * 16 + (threadIdx.x - 32)];
    __syncthreads();

    float a0 = 0.0f, a1 = 0.0f, a2 = 0.0f, a3 = 0.0f;
    const __half* eo = g_eo + (size_t)b * EDIM + e;

    #pragma unroll
    for (int j = 0; j < 12; j++) {
        float v = __half2float(eo[(size_t)j * BATCH * EDIM]);
        const int t = j >> 2;
        float gw = g[t * 8 + (j & 3)];
        if (t == 0)      a0 += gw * v;
        else if (t == 1) a1 += gw * v;
        else             a2 += gw * v;
        a3 += gs[j] * v;
    }
    #pragma unroll
    for (int s = 0; s < 4; s++) {
        float v = __half2float(eo[(size_t)(12 + s) * BATCH * EDIM]);
        a0 += g[0 * 8 + 4 + s] * v;
        a1 += g[1 * 8 + 4 + s] * v;
        a2 += g[2 * 8 + 4 + s] * v;
        a3 += gs[12 + s] * v;
    }

    const size_t o = (size_t)b * EDIM + e;
    const size_t plane = (size_t)BATCH * EDIM;
    out[o]             = a0;
    out[plane + o]     = a1;
    out[2 * plane + o] = a2;
    out[3 * plane + o] = a3;
}

// ---------------- host ----------------
extern "C" void kernel_launch(void* const* d_in, const int* in_sizes, int n_in,
                              void* d_out, int out_size)
{
    const float* x_tasks  = (const float*)d_in[0];
    const float* x_shared = (const float*)d_in[1];
    const float* W_spec1  = (const float*)d_in[2];
    const float* b_spec1  = (const float*)d_in[3];
    const float* W_spec2  = (const float*)d_in[4];
    const float* b_spec2  = (const float*)d_in[5];
    const float* W_sh1    = (const float*)d_in[6];
    const float* b_sh1    = (const float*)d_in[7];
    const float* W_sh2    = (const float*)d_in[8];
    const float* b_sh2    = (const float*)d_in[9];
    const float* W_gate   = (const float*)d_in[10];
    const float* b_gate   = (const float*)d_in[11];
    const float* W_gsh    = (const float*)d_in[12];
    const float* b_gsh    = (const float*)d_in[13];
    float* out = (float*)d_out;

    void *p_xh, *p_w1, *p_w2, *p_h;
    cudaGetSymbolAddress(&p_xh, g_xh);
    cudaGetSymbolAddress(&p_w1, g_w1);
    cudaGetSymbolAddress(&p_w2, g_w2);
    cudaGetSymbolAddress(&p_h, g_h);

    // one-time infra (created on the uncaptured correctness call; reused after)
    static bool inited = false;
    static cudaStream_t s1, s2;
    static cudaEvent_t ev_root, ev_w1, ev_w2, ev_gates;
    if (!inited) {
        cudaStreamCreateWithFlags(&s1, cudaStreamNonBlocking);
        cudaStreamCreateWithFlags(&s2, cudaStreamNonBlocking);
        cudaEventCreateWithFlags(&ev_root,  cudaEventDisableTiming);
        cudaEventCreateWithFlags(&ev_w1,    cudaEventDisableTiming);
        cudaEventCreateWithFlags(&ev_w2,    cudaEventDisableTiming);
        cudaEventCreateWithFlags(&ev_gates, cudaEventDisableTiming);
        cudaFuncSetAttribute(gemm_kernel<1024, HID, true>,
                             cudaFuncAttributeMaxDynamicSharedMemorySize, SMEM_TT);
        cudaFuncSetAttribute(gemm_kernel<512, EDIM, false>,
                             cudaFuncAttributeMaxDynamicSharedMemorySize, SMEM_TT);
        inited = true;
    }

    // fork side streams off the main (capture) stream
    cudaEventRecord(ev_root, 0);
    cudaStreamWaitEvent(s1, ev_root, 0);

    // phase 1 (bandwidth): convert_x (main) || wtrans1 (s1)
    convert_x_kernel<<<(4u * BATCH * DIM / 4) / 256, 256>>>(x_tasks, x_shared);
    wtrans_kernel<<<dim3(HID / 32, DIM / 32, NEXP), 256, 0, s1>>>(
        W_spec1, W_sh1, (__half*)p_w1, DIM, HID);
    cudaEventRecord(ev_w1, s1);

    // phase 2: gemm1 (main) with gates (s2, 128-thr co-resident) and wtrans2 (s1)
    cudaStreamWaitEvent(s2, ev_w1, 0);     // delay gates past the bandwidth phase
    gates_kernel<<<(TASK_WARPS + SH_WARPS) / 4, 128, 0, s2>>>(
        x_tasks, x_shared, W_gate, b_gate, W_gsh, b_gsh);
    cudaEventRecord(ev_gates, s2);

    wtrans_kernel<<<dim3(EDIM / 32, HID / 32, NEXP), 256, 0, s1>>>(
        W_spec2, W_sh2, (__half*)p_w2, HID, EDIM);
    cudaEventRecord(ev_w2, s1);

    cudaStreamWaitEvent(0, ev_w1, 0);
    gemm_kernel<1024, HID, true><<<dim3(HID / 256, BATCH / 128, NEXP), 256, SMEM_TT>>>(
        (const __half*)p_xh, (const __half*)p_w1, b_spec1, b_sh1);

    cudaStreamWaitEvent(0, ev_w2, 0);
    gemm_kernel<512, EDIM, false><<<dim3(EDIM / 256, BATCH / 128, NEXP), 256, SMEM_TT>>>(
        (const __half*)p_h, (const __half*)p_w2, b_spec2, b_sh2);

    cudaStreamWaitEvent(0, ev_gates, 0);
    combine_kernel<<<BATCH, 256>>>(out);
}

// round 16
// speedup vs baseline: 1.1307x; 1.1275x over previous
#include <cuda_runtime.h>
#include <cuda_bf16.h>
#include <cuda_fp16.h>
#include <cstdint>
#include <math.h>

#define BATCH 8192
#define DIM   1024
#define HID   512
#define EDIM  256
#define NEXP  16
#define TTASK 3

// ---------------- device scratch (no allocations allowed) ----------------
__device__ __half g_xh[(size_t)4 * BATCH * DIM];
__device__ __half g_w1[(size_t)NEXP * HID * DIM];           // [e][H][D] K-major fp16
__device__ __half g_w2[(size_t)NEXP * EDIM * HID];          // [e][E][H] K-major fp16
__device__ __half g_h [(size_t)NEXP * BATCH * HID];
__device__ __half g_eo[(size_t)NEXP * BATCH * EDIM];
__device__ float  g_gate[(size_t)TTASK * BATCH * 8];
__device__ float  g_gsh [(size_t)BATCH * 16];

// ---------------- low-level helpers ----------------
__device__ __forceinline__ uint32_t smem_u32(const void* p) {
    uint32_t a;
    asm("{ .reg .u64 t; cvta.to.shared.u64 t, %1; cvt.u32.u64 %0, t; }" : "=r"(a) : "l"(p));
    return a;
}
__device__ __forceinline__ void cp16(uint32_t s, const void* g) {
    asm volatile("cp.async.cg.shared.global [%0], [%1], 16;" :: "r"(s), "l"(g));
}
#define CP_COMMIT() asm volatile("cp.async.commit_group;" ::: "memory")
#define CP_WAIT2()  asm volatile("cp.async.wait_group 2;"  ::: "memory")

__device__ __forceinline__ void ldsm4(uint32_t (&r)[4], uint32_t a) {
    asm volatile("ldmatrix.sync.aligned.m8n8.x4.shared.b16 {%0,%1,%2,%3}, [%4];"
                 : "=r"(r[0]), "=r"(r[1]), "=r"(r[2]), "=r"(r[3]) : "r"(a));
}
__device__ __forceinline__ void mma_f16(float (&c)[4], const uint32_t (&a)[4],
                                        uint32_t b0, uint32_t b1) {
    asm volatile("mma.sync.aligned.m16n8k16.row.col.f32.f16.f16.f32 "
                 "{%0,%1,%2,%3}, {%4,%5,%6,%7}, {%8,%9}, {%0,%1,%2,%3};"
                 : "+f"(c[0]), "+f"(c[1]), "+f"(c[2]), "+f"(c[3])
                 : "r"(a[0]), "r"(a[1]), "r"(a[2]), "r"(a[3]), "r"(b0), "r"(b1));
}
__device__ __forceinline__ uint32_t pk2h(float a, float b) {
    __half2 t = __floats2half2_rn(a, b);
    return *reinterpret_cast<uint32_t*>(&t);
}

// ---------------- GEMM geometry ----------------
// BM=128, BN=128, BK=32 fp16, 128 threads = 4 warps of 64x64, 2 CTAs/SM
// (reg cap 256 -> fragment prefetch schedule survives). Rows padded to 80B.
#define RS       80u
#define A_SZ     (128u * RS)          // 10240 B
#define B_SZ     (128u * RS)          // 10240 B
#define OFF_B    A_SZ
#define STG_SZ   (A_SZ + B_SZ)        // 20480 B per stage
#define NSTG     5
#define BIAS_OFF (NSTG * STG_SZ)      // 102400
#define SMEM_TT  (BIAS_OFF + 1024)    // 103424; x2 CTA = 206848 < 227KB

// Y[128,128] tile of relu(A @ B^T + bias); warp tile 64x64.
// Cross-iteration fragment prefetch (R10/R13 structure).
template<int K, int OUTN, bool SPLIT_OUT>
__global__ void __launch_bounds__(128, 2) gemm_kernel(
    const __half* __restrict__ A, const __half* __restrict__ B,
    const float* __restrict__ bias_spec, const float* __restrict__ bias_sh)
{
    constexpr int KIT = K / 32;
    extern __shared__ __align__(16) char smem[];
    const uint32_t sb = smem_u32(smem);
    const int tid = threadIdx.x;
    const int e  = blockIdx.z;
    const int bm = blockIdx.y * 128;
    const int bn = blockIdx.x * 128;
    const int zA = SPLIT_OUT ? (e < 12 ? (e >> 2) : 3) : e;

    float* bias_sm = (float*)(smem + BIAS_OFF);
    {
        const float* bias = (e < 12) ? bias_spec + (size_t)e * OUTN
                                     : bias_sh  + (size_t)(e - 12) * OUTN;
        bias_sm[tid] = bias[bn + tid];
    }

    const __half* gA = A + ((size_t)zA * BATCH + bm) * K;
    const __half* gB = B + ((size_t)e * OUTN + bn) * K;

    // loader: A = 512 16B-chunks (4/thread), B = 512 chunks (4/thread)
    auto load_stage = [&](int s, int k0) {
        const uint32_t st = sb + (uint32_t)s * STG_SZ;
        #pragma unroll
        for (int i = 0; i < 4; i++) {
            const int c = tid + i * 128;     // 0..511
            const int row = c >> 2, q = c & 3;
            cp16(st + (uint32_t)row * RS + (uint32_t)q * 16,
                 gA + (size_t)row * K + k0 + q * 8);
        }
        #pragma unroll
        for (int i = 0; i < 4; i++) {
            const int c = tid + i * 128;
            const int row = c >> 2, q = c & 3;
            cp16(st + OFF_B + (uint32_t)row * RS + (uint32_t)q * 16,
                 gB + (size_t)row * K + k0 + q * 8);
        }
        CP_COMMIT();
    };

    load_stage(0, 0);
    load_stage(1, 32);
    load_stage(2, 64);
    load_stage(3, 96);

    const int wid = tid >> 5, L = tid & 31;
    const int mbase = (wid >> 1) * 64;   // warp row block (0,64)
    const int nbase = (wid & 1) * 64;    // warp col block (0,64)

    float acc[4][8][4];
    #pragma unroll
    for (int i = 0; i < 4; i++)
        #pragma unroll
        for (int j = 0; j < 8; j++)
            #pragma unroll
            for (int q = 0; q < 4; q++) acc[i][j][q] = 0.0f;

    const uint32_t aoff = (uint32_t)(mbase + (L & 15)) * RS + (uint32_t)(((L >> 4) & 1) * 16);
    const uint32_t boff = (uint32_t)(nbase + (L & 7) + ((L >> 4) & 1) * 8) * RS
                        + (uint32_t)(((L >> 3) & 1) * 16);

    uint32_t a0f[4][4], b0f[4][4], a1f[4][4], b1f[4][4];

    CP_WAIT2();
    __syncthreads();
    {
        const uint32_t ka = sb + aoff, kb = sb + OFF_B + boff;
        #pragma unroll
        for (int mt = 0; mt < 4; mt++) ldsm4(a0f[mt], ka + mt * (16 * RS));
        #pragma unroll
        for (int nt2 = 0; nt2 < 4; nt2++) ldsm4(b0f[nt2], kb + nt2 * (16 * RS));
    }

    int rstage = 0;
    for (int kt = 0; kt < KIT; kt++) {
        __syncthreads();
        const int wstage = (rstage + 4 >= NSTG) ? rstage - 1 : rstage + 4;  // (kt+4)%5
        if (kt + 4 < KIT) load_stage(wstage, (kt + 4) * 32);
        else              CP_COMMIT();   // keep group window sliding

        const uint32_t sbase = sb + (uint32_t)rstage * STG_SZ;
        const int nstage = (rstage == 4) ? 0 : rstage + 1;
        const uint32_t nb2 = sb + (uint32_t)nstage * STG_SZ;

        // load h1 frags of current tile (overlaps with h0 MMA burst)
        {
            const uint32_t ka = sbase + aoff + 32, kb = sbase + OFF_B + boff + 32;
            #pragma unroll
            for (int mt = 0; mt < 4; mt++) ldsm4(a1f[mt], ka + mt * (16 * RS));
            #pragma unroll
            for (int nt2 = 0; nt2 < 4; nt2++) ldsm4(b1f[nt2], kb + nt2 * (16 * RS));
        }
        // MMA on h0 frags (prefetched previous iteration)
        #pragma unroll
        for (int mt = 0; mt < 4; mt++)
            #pragma unroll
            for (int nt = 0; nt < 8; nt++)
                mma_f16(acc[mt][nt], a0f[mt],
                        b0f[nt >> 1][(nt & 1) * 2], b0f[nt >> 1][(nt & 1) * 2 + 1]);

        CP_WAIT2();                       // next tile's stage guaranteed complete
        if (kt + 1 < KIT) {
            const uint32_t ka = nb2 + aoff, kb = nb2 + OFF_B + boff;
            #pragma unroll
            for (int mt = 0; mt < 4; mt++) ldsm4(a0f[mt], ka + mt * (16 * RS));
            #pragma unroll
            for (int nt2 = 0; nt2 < 4; nt2++) ldsm4(b0f[nt2], kb + nt2 * (16 * RS));
        }
        // MMA on h1 frags
        #pragma unroll
        for (int mt = 0; mt < 4; mt++)
            #pragma unroll
            for (int nt = 0; nt < 8; nt++)
                mma_f16(acc[mt][nt], a1f[mt],
                        b1f[nt >> 1][(nt & 1) * 2], b1f[nt >> 1][(nt & 1) * 2 + 1]);

        rstage = nstage;
    }

    // ---------------- epilogue: bias + relu ----------------
    const int g  = L >> 2;
    const int t2 = (L & 3) * 2;
    #pragma unroll
    for (int mt = 0; mt < 4; mt++) {
        const int r0 = bm + mbase + mt * 16 + g;
        #pragma unroll
        for (int nt = 0; nt < 8; nt++) {
            const int col = nbase + nt * 8 + t2;
            const float b0v = bias_sm[col], b1v = bias_sm[col + 1];
            float v00 = fmaxf(acc[mt][nt][0] + b0v, 0.0f);
            float v01 = fmaxf(acc[mt][nt][1] + b1v, 0.0f);
            float v10 = fmaxf(acc[mt][nt][2] + b0v, 0.0f);
            float v11 = fmaxf(acc[mt][nt][3] + b1v, 0.0f);
            const size_t o0 = ((size_t)e * BATCH + r0) * OUTN + bn + col;
            const size_t o1 = o0 + (size_t)8 * OUTN;
            if (SPLIT_OUT) {
                *reinterpret_cast<uint32_t*>(&g_h[o0]) = pk2h(v00, v01);
                *reinterpret_cast<uint32_t*>(&g_h[o1]) = pk2h(v10, v11);
            } else {
                *reinterpret_cast<uint32_t*>(&g_eo[o0]) = pk2h(v00, v01);
                *reinterpret_cast<uint32_t*>(&g_eo[o1]) = pk2h(v10, v11);
            }
        }
    }
}

// ---------------- weight transpose + convert: [e][K][N] -> [e][N][K] fp16 ----
__global__ __launch_bounds__(256) void wtrans_kernel(
    const float* __restrict__ Wsp, const float* __restrict__ Wsh,
    __half* __restrict__ dst, int K, int N)
{
    __shared__ float t[32][33];
    const int e = blockIdx.z;
    const float* src = (e < 12) ? Wsp + (size_t)e * K * N
                                : Wsh + (size_t)(e - 12) * K * N;
    const int n0 = blockIdx.x * 32, k0 = blockIdx.y * 32;
    const int c = threadIdx.x & 31, r8 = threadIdx.x >> 5;
    #pragma unroll
    for (int rr = 0; rr < 32; rr += 8)
        t[r8 + rr][c] = src[(size_t)(k0 + r8 + rr) * N + n0 + c];
    __syncthreads();
    #pragma unroll
    for (int rr = 0; rr < 32; rr += 8) {
        float v = t[c][r8 + rr];
        size_t o = ((size_t)e * N + n0 + r8 + rr) * K + k0 + c;
        dst[o] = __float2half_rn(v);
    }
}

// ---------------- gates + x fp16 conversion fused (R13) ----------------
// 8 rows/warp (task), 4 rows/warp (shared). Gate math in fp32.
#define TASK_WARPS (TTASK * BATCH / 8)   // 3072
#define SH_WARPS   (BATCH / 4)           // 2048
__global__ __launch_bounds__(256) void gates_kernel(
    const float* __restrict__ x_tasks, const float* __restrict__ x_shared,
    const float* __restrict__ W_gate,  const float* __restrict__ b_gate,
    const float* __restrict__ W_gsh,   const float* __restrict__ b_gsh)
{
    const int warp = (blockIdx.x * blockDim.x + threadIdx.x) >> 5;
    const int lane = threadIdx.x & 31;

    if (warp < TASK_WARPS) {
        const int r0 = warp * 8;
        const int t  = r0 >> 13;
        const int b0 = r0 & (BATCH - 1);
        const float* x = x_tasks + ((size_t)t * BATCH + b0) * DIM;
        __half* xh = g_xh + ((size_t)t * BATCH + b0) * DIM;
        const float* W = W_gate + (size_t)t * DIM * 8;
        float s[8][8];
        #pragma unroll
        for (int r = 0; r < 8; r++)
            #pragma unroll
            for (int o = 0; o < 8; o++) s[r][o] = 0.0f;
        for (int d = lane; d < DIM; d += 32) {
            float4 w0 = *(const float4*)(W + (size_t)d * 8);
            float4 w1 = *(const float4*)(W + (size_t)d * 8 + 4);
            #pragma unroll
            for (int r = 0; r < 8; r++) {
                float xv = x[(size_t)r * DIM + d];
                xh[(size_t)r * DIM + d] = __float2half_rn(xv);
                s[r][0] += xv * w0.x; s[r][1] += xv * w0.y;
                s[r][2] += xv * w0.z; s[r][3] += xv * w0.w;
                s[r][4] += xv * w1.x; s[r][5] += xv * w1.y;
                s[r][6] += xv * w1.z; s[r][7] += xv * w1.w;
            }
        }
        #pragma unroll
        for (int r = 0; r < 8; r++)
            #pragma unroll
            for (int o = 0; o < 8; o++)
                #pragma unroll
                for (int off = 16; off > 0; off >>= 1)
                    s[r][o] += __shfl_xor_sync(0xffffffffu, s[r][o], off);
        if (lane == 0) {
            #pragma unroll
            for (int r = 0; r < 8; r++) {
                float mx = -1e30f;
                #pragma unroll
                for (int o = 0; o < 8; o++) { s[r][o] += b_gate[t * 8 + o]; mx = fmaxf(mx, s[r][o]); }
                float sum = 0.0f;
                #pragma unroll
                for (int o = 0; o < 8; o++) { s[r][o] = expf(s[r][o] - mx); sum += s[r][o]; }
                float inv = 1.0f / sum;
                #pragma unroll
                for (int o = 0; o < 8; o++)
                    g_gate[((size_t)t * BATCH + b0 + r) * 8 + o] = s[r][o] * inv;
            }
        }
    } else {
        const int b0 = (warp - TASK_WARPS) * 4;
        const float* x = x_shared + (size_t)b0 * DIM;
        __half* xh = g_xh + ((size_t)3 * BATCH + b0) * DIM;
        float s[4][16];
        #pragma unroll
        for (int r = 0; r < 4; r++)
            #pragma unroll
            for (int o = 0; o < 16; o++) s[r][o] = 0.0f;
        for (int d = lane; d < DIM; d += 32) {
            float4 w0 = *(const float4*)(W_gsh + (size_t)d * 16);
            float4 w1 = *(const float4*)(W_gsh + (size_t)d * 16 + 4);
            float4 w2 = *(const float4*)(W_gsh + (size_t)d * 16 + 8);
            float4 w3 = *(const float4*)(W_gsh + (size_t)d * 16 + 12);
            #pragma unroll
            for (int r = 0; r < 4; r++) {
                float xv = x[(size_t)r * DIM + d];
                xh[(size_t)r * DIM + d] = __float2half_rn(xv);
                s[r][ 0] += xv * w0.x; s[r][ 1] += xv * w0.y; s[r][ 2] += xv * w0.z; s[r][ 3] += xv * w0.w;
                s[r][ 4] += xv * w1.x; s[r][ 5] += xv * w1.y; s[r][ 6] += xv * w1.z; s[r][ 7] += xv * w1.w;
                s[r][ 8] += xv * w2.x; s[r][ 9] += xv * w2.y; s[r][10] += xv * w2.z; s[r][11] += xv * w2.w;
                s[r][12] += xv * w3.x; s[r][13] += xv * w3.y; s[r][14] += xv * w3.z; s[r][15] += xv * w3.w;
            }
        }
        #pragma unroll
        for (int r = 0; r < 4; r++)
            #pragma unroll
            for (int o = 0; o < 16; o++)
                #pragma unroll
                for (int off = 16; off > 0; off >>= 1)
                    s[r][o] += __shfl_xor_sync(0xffffffffu, s[r][o], off);
        if (lane == 0) {
            #pragma unroll
            for (int r = 0; r < 4; r++) {
                float mx = -1e30f;
                #pragma unroll
                for (int o = 0; o < 16; o++) { s[r][o] += b_gsh[o]; mx = fmaxf(mx, s[r][o]); }
                float sum = 0.0f;
                #pragma unroll
                for (int o = 0; o < 16; o++) { s[r][o] = expf(s[r][o] - mx); sum += s[r][o]; }
                float inv = 1.0f / sum;
                #pragma unroll
                for (int o = 0; o < 16; o++)
                    g_gsh[(size_t)(b0 + r) * 16 + o] = s[r][o] * inv;
            }
        }
    }
}

// ---------------- combine (eo in fp16) ----------------
__global__ __launch_bounds__(256) void combine_kernel(float* __restrict__ out)
{
    const int b = blockIdx.x;
    const int e = threadIdx.x;
    __shared__ float g[24];
    __shared__ float gs[16];

    if (threadIdx.x < 24)
        g[threadIdx.x] = g_gate[(size_t)(threadIdx.x >> 3) * BATCH * 8
                                + (size_t)b * 8 + (threadIdx.x & 7)];
    if (threadIdx.x >= 32 && threadIdx.x < 48)
        gs[threadIdx.x - 32] = g_gsh[(size_t)b * 16 + (threadIdx.x - 32)];
    __syncthreads();

    float a0 = 0.0f, a1 = 0.0f, a2 = 0.0f, a3 = 0.0f;
    const __half* eo = g_eo + (size_t)b * EDIM + e;

    #pragma unroll
    for (int j = 0; j < 12; j++) {
        float v = __half2float(eo[(size_t)j * BATCH * EDIM]);
        const int t = j >> 2;
        float gw = g[t * 8 + (j & 3)];
        if (t == 0)      a0 += gw * v;
        else if (t == 1) a1 += gw * v;
        else             a2 += gw * v;
        a3 += gs[j] * v;
    }
    #pragma unroll
    for (int s = 0; s < 4; s++) {
        float v = __half2float(eo[(size_t)(12 + s) * BATCH * EDIM]);
        a0 += g[0 * 8 + 4 + s] * v;
        a1 += g[1 * 8 + 4 + s] * v;
        a2 += g[2 * 8 + 4 + s] * v;
        a3 += gs[12 + s] * v;
    }

    const size_t o = (size_t)b * EDIM + e;
    const size_t plane = (size_t)BATCH * EDIM;
    out[o]             = a0;
    out[plane + o]     = a1;
    out[2 * plane + o] = a2;
    out[3 * plane + o] = a3;
}

// ---------------- host (single stream, R13 order) ----------------
extern "C" void kernel_launch(void* const* d_in, const int* in_sizes, int n_in,
                              void* d_out, int out_size)
{
    const float* x_tasks  = (const float*)d_in[0];
    const float* x_shared = (const float*)d_in[1];
    const float* W_spec1  = (const float*)d_in[2];
    const float* b_spec1  = (const float*)d_in[3];
    const float* W_spec2  = (const float*)d_in[4];
    const float* b_spec2  = (const float*)d_in[5];
    const float* W_sh1    = (const float*)d_in[6];
    const float* b_sh1    = (const float*)d_in[7];
    const float* W_sh2    = (const float*)d_in[8];
    const float* b_sh2    = (const float*)d_in[9];
    const float* W_gate   = (const float*)d_in[10];
    const float* b_gate   = (const float*)d_in[11];
    const float* W_gsh    = (const float*)d_in[12];
    const float* b_gsh    = (const float*)d_in[13];
    float* out = (float*)d_out;

    void *p_xh, *p_w1, *p_w2, *p_h;
    cudaGetSymbolAddress(&p_xh, g_xh);
    cudaGetSymbolAddress(&p_w1, g_w1);
    cudaGetSymbolAddress(&p_w2, g_w2);
    cudaGetSymbolAddress(&p_h, g_h);

    cudaFuncSetAttribute(gemm_kernel<1024, HID, true>,
                         cudaFuncAttributeMaxDynamicSharedMemorySize, SMEM_TT);
    cudaFuncSetAttribute(gemm_kernel<512, EDIM, false>,
                         cudaFuncAttributeMaxDynamicSharedMemorySize, SMEM_TT);

    // gates also produces g_xh (fp16 x) — must precede gemm1
    gates_kernel<<<(TASK_WARPS + SH_WARPS) / 8, 256>>>(
        x_tasks, x_shared, W_gate, b_gate, W_gsh, b_gsh);
    wtrans_kernel<<<dim3(HID / 32, DIM / 32, NEXP), 256>>>(
        W_spec1, W_sh1, (__half*)p_w1, DIM, HID);
    wtrans_kernel<<<dim3(EDIM / 32, HID / 32, NEXP), 256>>>(
        W_spec2, W_sh2, (__half*)p_w2, HID, EDIM);

    gemm_kernel<1024, HID, true><<<dim3(HID / 128, BATCH / 128, NEXP), 128, SMEM_TT>>>(
        (const __half*)p_xh, (const __half*)p_w1, b_spec1, b_sh1);
    gemm_kernel<512, EDIM, false><<<dim3(EDIM / 128, BATCH / 128, NEXP), 128, SMEM_TT>>>(
        (const __half*)p_h, (const __half*)p_w2, b_spec2, b_sh2);

    combine_kernel<<<BATCH, 256>>>(out);
}

// round 17
// speedup vs baseline: 1.1309x; 1.0002x over previous
#include <cuda_runtime.h>
#include <cuda_bf16.h>
#include <cuda_fp16.h>
#include <cstdint>
#include <math.h>

#define BATCH 8192
#define DIM   1024
#define HID   512
#define EDIM  256
#define NEXP  16
#define TTASK 3

// ---------------- device scratch (no allocations allowed) ----------------
__device__ __half g_xh[(size_t)4 * BATCH * DIM];
__device__ __half g_w1[(size_t)NEXP * HID * DIM];           // [e][H][D] K-major fp16
__device__ __half g_w2[(size_t)NEXP * EDIM * HID];          // [e][E][H] K-major fp16
__device__ __half g_h [(size_t)NEXP * BATCH * HID];
__device__ __half g_eo[(size_t)NEXP * BATCH * EDIM];
__device__ float  g_gate[(size_t)TTASK * BATCH * 8];
__device__ float  g_gsh [(size_t)BATCH * 16];

// ---------------- low-level helpers ----------------
__device__ __forceinline__ uint32_t smem_u32(const void* p) {
    uint32_t a;
    asm("{ .reg .u64 t; cvta.to.shared.u64 t, %1; cvt.u32.u64 %0, t; }" : "=r"(a) : "l"(p));
    return a;
}
__device__ __forceinline__ void cp16(uint32_t s, const void* g) {
    asm volatile("cp.async.cg.shared.global [%0], [%1], 16;" :: "r"(s), "l"(g));
}
#define CP_COMMIT() asm volatile("cp.async.commit_group;" ::: "memory")
#define CP_WAIT2()  asm volatile("cp.async.wait_group 2;"  ::: "memory")

__device__ __forceinline__ void ldsm4(uint32_t (&r)[4], uint32_t a) {
    asm volatile("ldmatrix.sync.aligned.m8n8.x4.shared.b16 {%0,%1,%2,%3}, [%4];"
                 : "=r"(r[0]), "=r"(r[1]), "=r"(r[2]), "=r"(r[3]) : "r"(a));
}
__device__ __forceinline__ void mma_f16(float (&c)[4], const uint32_t (&a)[4],
                                        uint32_t b0, uint32_t b1) {
    asm volatile("mma.sync.aligned.m16n8k16.row.col.f32.f16.f16.f32 "
                 "{%0,%1,%2,%3}, {%4,%5,%6,%7}, {%8,%9}, {%0,%1,%2,%3};"
                 : "+f"(c[0]), "+f"(c[1]), "+f"(c[2]), "+f"(c[3])
                 : "r"(a[0]), "r"(a[1]), "r"(a[2]), "r"(a[3]), "r"(b0), "r"(b1));
}
__device__ __forceinline__ uint32_t pk2h(float a, float b) {
    __half2 t = __floats2half2_rn(a, b);
    return *reinterpret_cast<uint32_t*>(&t);
}

// ---------------- GEMM geometry (R16: 4 warps of 64x64, 2 CTAs/SM) ----------
#define RS       80u
#define A_SZ     (128u * RS)
#define B_SZ     (128u * RS)
#define OFF_B    A_SZ
#define STG_SZ   (A_SZ + B_SZ)        // 20480 B per stage
#define NSTG     5
#define BIAS_OFF (NSTG * STG_SZ)      // 102400
#define SMEM_TT  (BIAS_OFF + 1024)    // 103424; x2 CTA = 206848 < 227KB

template<int K, int OUTN, bool SPLIT_OUT>
__global__ void __launch_bounds__(128, 2) gemm_kernel(
    const __half* __restrict__ A, const __half* __restrict__ B,
    const float* __restrict__ bias_spec, const float* __restrict__ bias_sh)
{
    constexpr int KIT = K / 32;
    extern __shared__ __align__(16) char smem[];
    const uint32_t sb = smem_u32(smem);
    const int tid = threadIdx.x;
    const int e  = blockIdx.z;
    const int bm = blockIdx.y * 128;
    const int bn = blockIdx.x * 128;
    const int zA = SPLIT_OUT ? (e < 12 ? (e >> 2) : 3) : e;

    float* bias_sm = (float*)(smem + BIAS_OFF);
    {
        const float* bias = (e < 12) ? bias_spec + (size_t)e * OUTN
                                     : bias_sh  + (size_t)(e - 12) * OUTN;
        bias_sm[tid] = bias[bn + tid];
    }

    const __half* gA = A + ((size_t)zA * BATCH + bm) * K;
    const __half* gB = B + ((size_t)e * OUTN + bn) * K;

    auto load_stage = [&](int s, int k0) {
        const uint32_t st = sb + (uint32_t)s * STG_SZ;
        #pragma unroll
        for (int i = 0; i < 4; i++) {
            const int c = tid + i * 128;
            const int row = c >> 2, q = c & 3;
            cp16(st + (uint32_t)row * RS + (uint32_t)q * 16,
                 gA + (size_t)row * K + k0 + q * 8);
        }
        #pragma unroll
        for (int i = 0; i < 4; i++) {
            const int c = tid + i * 128;
            const int row = c >> 2, q = c & 3;
            cp16(st + OFF_B + (uint32_t)row * RS + (uint32_t)q * 16,
                 gB + (size_t)row * K + k0 + q * 8);
        }
        CP_COMMIT();
    };

    load_stage(0, 0);
    load_stage(1, 32);
    load_stage(2, 64);
    load_stage(3, 96);

    const int wid = tid >> 5, L = tid & 31;
    const int mbase = (wid >> 1) * 64;
    const int nbase = (wid & 1) * 64;

    float acc[4][8][4];
    #pragma unroll
    for (int i = 0; i < 4; i++)
        #pragma unroll
        for (int j = 0; j < 8; j++)
            #pragma unroll
            for (int q = 0; q < 4; q++) acc[i][j][q] = 0.0f;

    const uint32_t aoff = (uint32_t)(mbase + (L & 15)) * RS + (uint32_t)(((L >> 4) & 1) * 16);
    const uint32_t boff = (uint32_t)(nbase + (L & 7) + ((L >> 4) & 1) * 8) * RS
                        + (uint32_t)(((L >> 3) & 1) * 16);

    uint32_t a0f[4][4], b0f[4][4], a1f[4][4], b1f[4][4];

    CP_WAIT2();
    __syncthreads();
    {
        const uint32_t ka = sb + aoff, kb = sb + OFF_B + boff;
        #pragma unroll
        for (int mt = 0; mt < 4; mt++) ldsm4(a0f[mt], ka + mt * (16 * RS));
        #pragma unroll
        for (int nt2 = 0; nt2 < 4; nt2++) ldsm4(b0f[nt2], kb + nt2 * (16 * RS));
    }

    int rstage = 0;
    for (int kt = 0; kt < KIT; kt++) {
        __syncthreads();
        const int wstage = (rstage + 4 >= NSTG) ? rstage - 1 : rstage + 4;  // (kt+4)%5
        if (kt + 4 < KIT) load_stage(wstage, (kt + 4) * 32);
        else              CP_COMMIT();

        const uint32_t sbase = sb + (uint32_t)rstage * STG_SZ;
        const int nstage = (rstage == 4) ? 0 : rstage + 1;
        const uint32_t nb2 = sb + (uint32_t)nstage * STG_SZ;

        {
            const uint32_t ka = sbase + aoff + 32, kb = sbase + OFF_B + boff + 32;
            #pragma unroll
            for (int mt = 0; mt < 4; mt++) ldsm4(a1f[mt], ka + mt * (16 * RS));
            #pragma unroll
            for (int nt2 = 0; nt2 < 4; nt2++) ldsm4(b1f[nt2], kb + nt2 * (16 * RS));
        }
        #pragma unroll
        for (int mt = 0; mt < 4; mt++)
            #pragma unroll
            for (int nt = 0; nt < 8; nt++)
                mma_f16(acc[mt][nt], a0f[mt],
                        b0f[nt >> 1][(nt & 1) * 2], b0f[nt >> 1][(nt & 1) * 2 + 1]);

        CP_WAIT2();
        if (kt + 1 < KIT) {
            const uint32_t ka = nb2 + aoff, kb = nb2 + OFF_B + boff;
            #pragma unroll
            for (int mt = 0; mt < 4; mt++) ldsm4(a0f[mt], ka + mt * (16 * RS));
            #pragma unroll
            for (int nt2 = 0; nt2 < 4; nt2++) ldsm4(b0f[nt2], kb + nt2 * (16 * RS));
        }
        #pragma unroll
        for (int mt = 0; mt < 4; mt++)
            #pragma unroll
            for (int nt = 0; nt < 8; nt++)
                mma_f16(acc[mt][nt], a1f[mt],
                        b1f[nt >> 1][(nt & 1) * 2], b1f[nt >> 1][(nt & 1) * 2 + 1]);

        rstage = nstage;
    }

    // ---------------- epilogue: bias + relu ----------------
    const int g  = L >> 2;
    const int t2 = (L & 3) * 2;
    #pragma unroll
    for (int mt = 0; mt < 4; mt++) {
        const int r0 = bm + mbase + mt * 16 + g;
        #pragma unroll
        for (int nt = 0; nt < 8; nt++) {
            const int col = nbase + nt * 8 + t2;
            const float b0v = bias_sm[col], b1v = bias_sm[col + 1];
            float v00 = fmaxf(acc[mt][nt][0] + b0v, 0.0f);
            float v01 = fmaxf(acc[mt][nt][1] + b1v, 0.0f);
            float v10 = fmaxf(acc[mt][nt][2] + b0v, 0.0f);
            float v11 = fmaxf(acc[mt][nt][3] + b1v, 0.0f);
            const size_t o0 = ((size_t)e * BATCH + r0) * OUTN + bn + col;
            const size_t o1 = o0 + (size_t)8 * OUTN;
            if (SPLIT_OUT) {
                *reinterpret_cast<uint32_t*>(&g_h[o0]) = pk2h(v00, v01);
                *reinterpret_cast<uint32_t*>(&g_h[o1]) = pk2h(v10, v11);
            } else {
                *reinterpret_cast<uint32_t*>(&g_eo[o0]) = pk2h(v00, v01);
                *reinterpret_cast<uint32_t*>(&g_eo[o1]) = pk2h(v10, v11);
            }
        }
    }
}

// ---------------- weight transpose + convert: [e][K][N] -> [e][N][K] fp16 ----
__global__ __launch_bounds__(256) void wtrans_kernel(
    const float* __restrict__ Wsp, const float* __restrict__ Wsh,
    __half* __restrict__ dst, int K, int N)
{
    __shared__ float t[32][33];
    const int e = blockIdx.z;
    const float* src = (e < 12) ? Wsp + (size_t)e * K * N
                                : Wsh + (size_t)(e - 12) * K * N;
    const int n0 = blockIdx.x * 32, k0 = blockIdx.y * 32;
    const int c = threadIdx.x & 31, r8 = threadIdx.x >> 5;
    #pragma unroll
    for (int rr = 0; rr < 32; rr += 8)
        t[r8 + rr][c] = src[(size_t)(k0 + r8 + rr) * N + n0 + c];
    __syncthreads();
    #pragma unroll
    for (int rr = 0; rr < 32; rr += 8) {
        float v = t[c][r8 + rr];
        size_t o = ((size_t)e * N + n0 + r8 + rr) * K + k0 + c;
        dst[o] = __float2half_rn(v);
    }
}

// ---------------- gates + x fp16 conversion fused, float4 inner loop --------
// Task warps: 8 rows; shared warps: 4 rows. Lane owns d = it*128 + lane*4.
#define TASK_WARPS (TTASK * BATCH / 8)   // 3072
#define SH_WARPS   (BATCH / 4)           // 2048
__global__ __launch_bounds__(256) void gates_kernel(
    const float* __restrict__ x_tasks, const float* __restrict__ x_shared,
    const float* __restrict__ W_gate,  const float* __restrict__ b_gate,
    const float* __restrict__ W_gsh,   const float* __restrict__ b_gsh)
{
    const int warp = (blockIdx.x * blockDim.x + threadIdx.x) >> 5;
    const int lane = threadIdx.x & 31;

    if (warp < TASK_WARPS) {
        const int r0 = warp * 8;
        const int t  = r0 >> 13;
        const int b0 = r0 & (BATCH - 1);
        const float* x = x_tasks + ((size_t)t * BATCH + b0) * DIM;
        __half* xh = g_xh + ((size_t)t * BATCH + b0) * DIM;
        const float* W = W_gate + (size_t)t * DIM * 8;
        float s[8][8];
        #pragma unroll
        for (int r = 0; r < 8; r++)
            #pragma unroll
            for (int o = 0; o < 8; o++) s[r][o] = 0.0f;

        for (int it = 0; it < DIM / 128; it++) {
            const int d0 = it * 128 + lane * 4;
            float4 wA[4], wB[4];
            #pragma unroll
            for (int dd = 0; dd < 4; dd++) {
                wA[dd] = *(const float4*)(W + (size_t)(d0 + dd) * 8);
                wB[dd] = *(const float4*)(W + (size_t)(d0 + dd) * 8 + 4);
            }
            #pragma unroll
            for (int r = 0; r < 8; r++) {
                float4 xv = *(const float4*)(x + (size_t)r * DIM + d0);
                uint2 H = { pk2h(xv.x, xv.y), pk2h(xv.z, xv.w) };
                *reinterpret_cast<uint2*>(&xh[(size_t)r * DIM + d0]) = H;
                const float xc[4] = { xv.x, xv.y, xv.z, xv.w };
                #pragma unroll
                for (int dd = 0; dd < 4; dd++) {
                    s[r][0] += xc[dd] * wA[dd].x; s[r][1] += xc[dd] * wA[dd].y;
                    s[r][2] += xc[dd] * wA[dd].z; s[r][3] += xc[dd] * wA[dd].w;
                    s[r][4] += xc[dd] * wB[dd].x; s[r][5] += xc[dd] * wB[dd].y;
                    s[r][6] += xc[dd] * wB[dd].z; s[r][7] += xc[dd] * wB[dd].w;
                }
            }
        }
        #pragma unroll
        for (int r = 0; r < 8; r++)
            #pragma unroll
            for (int o = 0; o < 8; o++)
                #pragma unroll
                for (int off = 16; off > 0; off >>= 1)
                    s[r][o] += __shfl_xor_sync(0xffffffffu, s[r][o], off);
        if (lane == 0) {
            #pragma unroll
            for (int r = 0; r < 8; r++) {
                float mx = -1e30f;
                #pragma unroll
                for (int o = 0; o < 8; o++) { s[r][o] += b_gate[t * 8 + o]; mx = fmaxf(mx, s[r][o]); }
                float sum = 0.0f;
                #pragma unroll
                for (int o = 0; o < 8; o++) { s[r][o] = expf(s[r][o] - mx); sum += s[r][o]; }
                float inv = 1.0f / sum;
                #pragma unroll
                for (int o = 0; o < 8; o++)
                    g_gate[((size_t)t * BATCH + b0 + r) * 8 + o] = s[r][o] * inv;
            }
        }
    } else {
        const int b0 = (warp - TASK_WARPS) * 4;
        const float* x = x_shared + (size_t)b0 * DIM;
        __half* xh = g_xh + ((size_t)3 * BATCH + b0) * DIM;
        float s[4][16];
        #pragma unroll
        for (int r = 0; r < 4; r++)
            #pragma unroll
            for (int o = 0; o < 16; o++) s[r][o] = 0.0f;

        for (int it = 0; it < DIM / 128; it++) {
            const int d0 = it * 128 + lane * 4;
            float4 w0[4], w1[4], w2[4], w3[4];
            #pragma unroll
            for (int dd = 0; dd < 4; dd++) {
                const float* Wd = W_gsh + (size_t)(d0 + dd) * 16;
                w0[dd] = *(const float4*)(Wd);
                w1[dd] = *(const float4*)(Wd + 4);
                w2[dd] = *(const float4*)(Wd + 8);
                w3[dd] = *(const float4*)(Wd + 12);
            }
            #pragma unroll
            for (int r = 0; r < 4; r++) {
                float4 xv = *(const float4*)(x + (size_t)r * DIM + d0);
                uint2 H = { pk2h(xv.x, xv.y), pk2h(xv.z, xv.w) };
                *reinterpret_cast<uint2*>(&xh[(size_t)r * DIM + d0]) = H;
                const float xc[4] = { xv.x, xv.y, xv.z, xv.w };
                #pragma unroll
                for (int dd = 0; dd < 4; dd++) {
                    s[r][ 0] += xc[dd] * w0[dd].x; s[r][ 1] += xc[dd] * w0[dd].y;
                    s[r][ 2] += xc[dd] * w0[dd].z; s[r][ 3] += xc[dd] * w0[dd].w;
                    s[r][ 4] += xc[dd] * w1[dd].x; s[r][ 5] += xc[dd] * w1[dd].y;
                    s[r][ 6] += xc[dd] * w1[dd].z; s[r][ 7] += xc[dd] * w1[dd].w;
                    s[r][ 8] += xc[dd] * w2[dd].x; s[r][ 9] += xc[dd] * w2[dd].y;
                    s[r][10] += xc[dd] * w2[dd].z; s[r][11] += xc[dd] * w2[dd].w;
                    s[r][12] += xc[dd] * w3[dd].x; s[r][13] += xc[dd] * w3[dd].y;
                    s[r][14] += xc[dd] * w3[dd].z; s[r][15] += xc[dd] * w3[dd].w;
                }
            }
        }
        #pragma unroll
        for (int r = 0; r < 4; r++)
            #pragma unroll
            for (int o = 0; o < 16; o++)
                #pragma unroll
                for (int off = 16; off > 0; off >>= 1)
                    s[r][o] += __shfl_xor_sync(0xffffffffu, s[r][o], off);
        if (lane == 0) {
            #pragma unroll
            for (int r = 0; r < 4; r++) {
                float mx = -1e30f;
                #pragma unroll
                for (int o = 0; o < 16; o++) { s[r][o] += b_gsh[o]; mx = fmaxf(mx, s[r][o]); }
                float sum = 0.0f;
                #pragma unroll
                for (int o = 0; o < 16; o++) { s[r][o] = expf(s[r][o] - mx); sum += s[r][o]; }
                float inv = 1.0f / sum;
                #pragma unroll
                for (int o = 0; o < 16; o++)
                    g_gsh[(size_t)(b0 + r) * 16 + o] = s[r][o] * inv;
            }
        }
    }
}

// ---------------- combine (eo in fp16) ----------------
__global__ __launch_bounds__(256) void combine_kernel(float* __restrict__ out)
{
    const int b = blockIdx.x;
    const int e = threadIdx.x;
    __shared__ float g[24];
    __shared__ float gs[16];

    if (threadIdx.x < 24)
        g[threadIdx.x] = g_gate[(size_t)(threadIdx.x >> 3) * BATCH * 8
                                + (size_t)b * 8 + (threadIdx.x & 7)];
    if (threadIdx.x >= 32 && threadIdx.x < 48)
        gs[threadIdx.x - 32] = g_gsh[(size_t)b * 16 + (threadIdx.x - 32)];
    __syncthreads();

    float a0 = 0.0f, a1 = 0.0f, a2 = 0.0f, a3 = 0.0f;
    const __half* eo = g_eo + (size_t)b * EDIM + e;

    #pragma unroll
    for (int j = 0; j < 12; j++) {
        float v = __half2float(eo[(size_t)j * BATCH * EDIM]);
        const int t = j >> 2;
        float gw = g[t * 8 + (j & 3)];
        if (t == 0)      a0 += gw * v;
        else if (t == 1) a1 += gw * v;
        else             a2 += gw * v;
        a3 += gs[j] * v;
    }
    #pragma unroll
    for (int s = 0; s < 4; s++) {
        float v = __half2float(eo[(size_t)(12 + s) * BATCH * EDIM]);
        a0 += g[0 * 8 + 4 + s] * v;
        a1 += g[1 * 8 + 4 + s] * v;
        a2 += g[2 * 8 + 4 + s] * v;
        a3 += gs[12 + s] * v;
    }

    const size_t o = (size_t)b * EDIM + e;
    const size_t plane = (size_t)BATCH * EDIM;
    out[o]             = a0;
    out[plane + o]     = a1;
    out[2 * plane + o] = a2;
    out[3 * plane + o] = a3;
}

// ---------------- host (single stream) ----------------
extern "C" void kernel_launch(void* const* d_in, const int* in_sizes, int n_in,
                              void* d_out, int out_size)
{
    const float* x_tasks  = (const float*)d_in[0];
    const float* x_shared = (const float*)d_in[1];
    const float* W_spec1  = (const float*)d_in[2];
    const float* b_spec1  = (const float*)d_in[3];
    const float* W_spec2  = (const float*)d_in[4];
    const float* b_spec2  = (const float*)d_in[5];
    const float* W_sh1    = (const float*)d_in[6];
    const float* b_sh1    = (const float*)d_in[7];
    const float* W_sh2    = (const float*)d_in[8];
    const float* b_sh2    = (const float*)d_in[9];
    const float* W_gate   = (const float*)d_in[10];
    const float* b_gate   = (const float*)d_in[11];
    const float* W_gsh    = (const float*)d_in[12];
    const float* b_gsh    = (const float*)d_in[13];
    float* out = (float*)d_out;

    void *p_xh, *p_w1, *p_w2, *p_h;
    cudaGetSymbolAddress(&p_xh, g_xh);
    cudaGetSymbolAddress(&p_w1, g_w1);
    cudaGetSymbolAddress(&p_w2, g_w2);
    cudaGetSymbolAddress(&p_h, g_h);

    cudaFuncSetAttribute(gemm_kernel<1024, HID, true>,
                         cudaFuncAttributeMaxDynamicSharedMemorySize, SMEM_TT);
    cudaFuncSetAttribute(gemm_kernel<512, EDIM, false>,
                         cudaFuncAttributeMaxDynamicSharedMemorySize, SMEM_TT);

    // gates also produces g_xh (fp16 x) — must precede gemm1
    gates_kernel<<<(TASK_WARPS + SH_WARPS) / 8, 256>>>(
        x_tasks, x_shared, W_gate, b_gate, W_gsh, b_gsh);
    wtrans_kernel<<<dim3(HID / 32, DIM / 32, NEXP), 256>>>(
        W_spec1, W_sh1, (__half*)p_w1, DIM, HID);
    wtrans_kernel<<<dim3(EDIM / 32, HID / 32, NEXP), 256>>>(
        W_spec2, W_sh2, (__half*)p_w2, HID, EDIM);

    gemm_kernel<1024, HID, true><<<dim3(HID / 128, BATCH / 128, NEXP), 128, SMEM_TT>>>(
        (const __half*)p_xh, (const __half*)p_w1, b_spec1, b_sh1);
    gemm_kernel<512, EDIM, false><<<dim3(EDIM / 128, BATCH / 128, NEXP), 128, SMEM_TT>>>(
        (const __half*)p_h, (const __half*)p_w2, b_spec2, b_sh2);

    combine_kernel<<<BATCH, 256>>>(out);
}